// round 9
// baseline (speedup 1.0000x reference)
#include <cuda_runtime.h>
#include <cuda_fp16.h>
#include <cuda_bf16.h>

#define BB 2
#define NC 128
#define NS 2048
#define NZ 256
#define NX 256
#define KK 4
#define MM (NZ * NX)

#define DTHREADS 512                  // das block size; block owns 512 pixels
#define NS4 (NS / 2)                  // uint4 (=2 samples) per channel row: 1024
#define BLOCKS_PER_BATCH (MM / DTHREADS)   // 128

// fp16 rf: sample s of channel row = 4 halves (8B). Stored as uint4 pairs of
// samples for coalesced staging: d_rf16[(b*NC+c)*NS4 + i] covers samples 2i,2i+1.
__device__ uint4 d_rf16[BB * NC * NS4];

__global__ void pack_kernel(const float* __restrict__ rf) {
    const int t = blockIdx.x * blockDim.x + threadIdx.x;   // 0 .. BB*NC*NS4-1
    if (t >= BB * NC * NS4) return;
    const int row = t >> 10;            // channel-row index (b*NC+c)
    const int pos = t & (NS4 - 1);      // uint4 position within row
    const float4* rf4 = (const float4*)rf + (size_t)row * NS;
    const float4 y0 = rf4[2 * pos + 0];
    const float4 y1 = rf4[2 * pos + 1];
    __half2 h0 = __floats2half2_rn(y0.x, y0.y);
    __half2 h1 = __floats2half2_rn(y0.z, y0.w);
    __half2 h2 = __floats2half2_rn(y1.x, y1.y);
    __half2 h3 = __floats2half2_rn(y1.z, y1.w);
    uint4 v;
    v.x = *(unsigned*)&h0;
    v.y = *(unsigned*)&h1;
    v.z = *(unsigned*)&h2;
    v.w = *(unsigned*)&h3;
    d_rf16[t] = v;
}

__global__ __launch_bounds__(DTHREADS) void das_kernel(
    const float* __restrict__ g,    // [B, NZ, NX, 3]
    const float* __restrict__ pr,   // [B, NC, 3]
    const float* __restrict__ p,    // [B, 4]
    float* __restrict__ out)        // [B, NZ, NX, K]
{
    __shared__ uint4 buf[2][NS4];   // double-buffered channel row: 2 x 16KB
    __shared__ float4 s_pr[NC];
    __shared__ float s_scale, s_base;

    const int tid = threadIdx.x;
    const int b = blockIdx.x / BLOCKS_PER_BATCH;
    const int m = (blockIdx.x % BLOCKS_PER_BATCH) * DTHREADS + tid;

    if (tid < NC) {
        const float* q = pr + ((size_t)b * NC + tid) * 3;
        s_pr[tid] = make_float4(q[0], q[1], q[2], 0.0f);
    }
    if (tid == 0) {
        const float c0 = p[b * 4 + 0];
        const float fs = p[b * 4 + 1];
        const float t0 = p[b * 4 + 2];
        s_scale = fs / c0;
        s_base  = fs * t0 / c0;
    }

    const float* gp = g + ((size_t)b * MM + m) * 3;
    const float gx = gp[0];
    const float gy = gp[1];
    const float gz = gp[2];

    const uint4* __restrict__ rfg = d_rf16 + (size_t)b * NC * NS4;

    // Stage channel 0; prefetch channel 1 into regs.
    {
        uint4 a0 = rfg[tid];
        uint4 a1 = rfg[tid + DTHREADS];
        buf[0][tid] = a0;
        buf[0][tid + DTHREADS] = a1;
    }
    uint4 n0 = rfg[NS4 + tid];
    uint4 n1 = rfg[NS4 + tid + DTHREADS];
    __syncthreads();   // params + buf0 visible

    const float scale = s_scale;
    const float base  = s_base;

    float ax = 0.0f, ay = 0.0f, az = 0.0f, aw = 0.0f;

    #pragma unroll 2
    for (int c = 0; c < NC; ++c) {
        // Write buffer for channel c+1 (data prefetched during iter c-1).
        // Safe: last reads of buf[(c+1)&1] were in iter c-1, ordered by its sync.
        if (c + 1 < NC) {
            buf[(c + 1) & 1][tid] = n0;
            buf[(c + 1) & 1][tid + DTHREADS] = n1;
        }
        // Prefetch channel c+2 (latency spans the whole iteration).
        if (c + 2 < NC) {
            n0 = rfg[(c + 2) * NS4 + tid];
            n1 = rfg[(c + 2) * NS4 + tid + DTHREADS];
        }

        // --- compute channel c from buf[c&1] ---
        const float4 pc = s_pr[c];
        const float dx = gx - pc.x;
        const float dy = gy - pc.y;
        const float dz = gz - pc.z;
        const float r2 = fmaf(dx, dx, fmaf(dy, dy, dz * dz));
        float drx;
        asm("sqrt.approx.f32 %0, %1;" : "=f"(drx) : "f"(r2));

        float s = fmaf(scale, drx + gz, base);
        s = fminf(fmaxf(s, 0.0f), (float)(NS - 1));
        const float i0f = fminf(floorf(s), (float)(NS - 2));
        const int   i0  = (int)i0f;
        const float w   = s - i0f;
        const float wm  = 1.0f - w;

        const uint2* row = (const uint2*)buf[c & 1];  // 8B per sample
        const uint2 t0v = row[i0];        // tap 0: 4 halves
        const uint2 t1v = row[i0 + 1];    // tap 1: 4 halves

        const float2 f0 = __half22float2(*(const __half2*)&t0v.x);
        const float2 f1 = __half22float2(*(const __half2*)&t0v.y);
        const float2 f2 = __half22float2(*(const __half2*)&t1v.x);
        const float2 f3 = __half22float2(*(const __half2*)&t1v.y);

        ax = fmaf(wm, f0.x, fmaf(w, f2.x, ax));
        ay = fmaf(wm, f0.y, fmaf(w, f2.y, ay));
        az = fmaf(wm, f1.x, fmaf(w, f3.x, az));
        aw = fmaf(wm, f1.y, fmaf(w, f3.y, aw));

        __syncthreads();   // single barrier: orders this iter's reads & writes
    }

    ((float4*)out)[(size_t)b * MM + m] = make_float4(ax, ay, az, aw);
}

extern "C" void kernel_launch(void* const* d_in, const int* in_sizes, int n_in,
                              void* d_out, int out_size) {
    const float* rf = (const float*)d_in[0];
    const float* g  = (const float*)d_in[1];
    const float* pr = (const float*)d_in[2];
    const float* p  = (const float*)d_in[3];
    float* out = (float*)d_out;

    pack_kernel<<<(BB * NC * NS4 + 255) / 256, 256>>>(rf);

    das_kernel<<<BB * BLOCKS_PER_BATCH, DTHREADS>>>(g, pr, p, out);
}

// round 10
// speedup vs baseline: 1.1708x; 1.1708x over previous
#include <cuda_runtime.h>
#include <cuda_fp16.h>
#include <cuda_bf16.h>

#define BB 2
#define NC 128
#define NS 2048
#define NZ 256
#define NX 256
#define KK 4
#define MM (NZ * NX)

#define DTHREADS 1024
#define PXB 2048                         // pixels per block (2 per thread)
#define NS4 (NS / 2)                     // uint4 (=2 samples) per channel row
#define CHALF (NC / 2)                   // channels per block (split 2-way)
#define PTILES (MM / PXB)                // 32 pixel tiles per batch

// fp16 rf rows, 8B/sample, stored as uint4 = 2 samples for coalesced staging.
__device__ uint4  d_rf16[BB * NC * NS4];
// Partial sums: [half][b][pixel] as float4
__device__ float4 d_part[2 * BB * MM];

__global__ void pack_kernel(const float* __restrict__ rf) {
    const int t = blockIdx.x * blockDim.x + threadIdx.x;   // 0 .. BB*NC*NS4-1
    if (t >= BB * NC * NS4) return;
    const int row = t >> 10;            // channel-row index (b*NC+c)
    const int pos = t & (NS4 - 1);
    const float4* rf4 = (const float4*)rf + (size_t)row * NS;
    const float4 y0 = rf4[2 * pos + 0];
    const float4 y1 = rf4[2 * pos + 1];
    __half2 h0 = __floats2half2_rn(y0.x, y0.y);
    __half2 h1 = __floats2half2_rn(y0.z, y0.w);
    __half2 h2 = __floats2half2_rn(y1.x, y1.y);
    __half2 h3 = __floats2half2_rn(y1.z, y1.w);
    uint4 v;
    v.x = *(unsigned*)&h0;
    v.y = *(unsigned*)&h1;
    v.z = *(unsigned*)&h2;
    v.w = *(unsigned*)&h3;
    d_rf16[t] = v;
}

__global__ __launch_bounds__(DTHREADS) void das_kernel(
    const float* __restrict__ g,    // [B, NZ, NX, 3]
    const float* __restrict__ pr,   // [B, NC, 3]
    const float* __restrict__ p)    // [B, 4]
{
    __shared__ uint4 buf[2][NS4];   // double-buffered channel row: 2 x 16KB
    __shared__ float4 s_pr[NC];
    __shared__ float s_scale, s_base;

    const int tid = threadIdx.x;
    // grid: blockIdx.x = ((b*PTILES + tile)*2 + half)
    const int half = blockIdx.x & 1;
    const int tile = (blockIdx.x >> 1) & (PTILES - 1);
    const int b    = blockIdx.x >> 7;            // /(2*PTILES)=64... PTILES=32 -> >>6? careful
    // PTILES=32 -> 2*PTILES=64 -> b = blockIdx.x / 64
    const int bb   = blockIdx.x / (2 * PTILES);

    const int m0 = tile * PXB + tid;
    const int m1 = m0 + DTHREADS;
    const int c0 = half * CHALF;

    if (tid < NC) {
        const float* q = pr + ((size_t)bb * NC + tid) * 3;
        s_pr[tid] = make_float4(q[0], q[1], q[2], 0.0f);
    }
    if (tid == 0) {
        const float cc = p[bb * 4 + 0];
        const float fs = p[bb * 4 + 1];
        const float t0 = p[bb * 4 + 2];
        s_scale = fs / cc;
        s_base  = fs * t0 / cc;
    }

    const float* gp0 = g + ((size_t)bb * MM + m0) * 3;
    const float* gp1 = g + ((size_t)bb * MM + m1) * 3;
    const float gx0 = gp0[0], gy0 = gp0[1], gz0 = gp0[2];
    const float gx1 = gp1[0], gy1 = gp1[1], gz1 = gp1[2];

    const uint4* __restrict__ rfg = d_rf16 + ((size_t)bb * NC + c0) * NS4;

    // Stage channel c0; prefetch c0+1 into regs.
    buf[0][tid] = rfg[tid];
    uint4 nxt = rfg[NS4 + tid];
    __syncthreads();   // params + buf0 visible

    const float scale = s_scale;
    const float base  = s_base;

    float4 a0 = make_float4(0.f, 0.f, 0.f, 0.f);
    float4 a1 = make_float4(0.f, 0.f, 0.f, 0.f);

    #pragma unroll 2
    for (int c = 0; c < CHALF; ++c) {
        // Write buffer for channel c+1 (prefetched during iter c-1).
        if (c + 1 < CHALF) buf[(c + 1) & 1][tid] = nxt;
        // Prefetch channel c+2.
        if (c + 2 < CHALF) nxt = rfg[(c + 2) * NS4 + tid];

        const float4 pc = s_pr[c0 + c];
        const uint2* row = (const uint2*)buf[c & 1];

        // pixel 0
        {
            const float dx = gx0 - pc.x, dy = gy0 - pc.y, dz = gz0 - pc.z;
            const float r2 = fmaf(dx, dx, fmaf(dy, dy, dz * dz));
            float drx; asm("sqrt.approx.f32 %0, %1;" : "=f"(drx) : "f"(r2));
            float s = fmaf(scale, drx + gz0, base);
            s = fminf(fmaxf(s, 0.0f), (float)(NS - 1));
            const float i0f = fminf(floorf(s), (float)(NS - 2));
            const int   i0  = (int)i0f;
            const float w  = s - i0f;
            const float wm = 1.0f - w;
            const uint2 t0v = row[i0];
            const uint2 t1v = row[i0 + 1];
            const float2 f0 = __half22float2(*(const __half2*)&t0v.x);
            const float2 f1 = __half22float2(*(const __half2*)&t0v.y);
            const float2 f2 = __half22float2(*(const __half2*)&t1v.x);
            const float2 f3 = __half22float2(*(const __half2*)&t1v.y);
            a0.x = fmaf(wm, f0.x, fmaf(w, f2.x, a0.x));
            a0.y = fmaf(wm, f0.y, fmaf(w, f2.y, a0.y));
            a0.z = fmaf(wm, f1.x, fmaf(w, f3.x, a0.z));
            a0.w = fmaf(wm, f1.y, fmaf(w, f3.y, a0.w));
        }
        // pixel 1
        {
            const float dx = gx1 - pc.x, dy = gy1 - pc.y, dz = gz1 - pc.z;
            const float r2 = fmaf(dx, dx, fmaf(dy, dy, dz * dz));
            float drx; asm("sqrt.approx.f32 %0, %1;" : "=f"(drx) : "f"(r2));
            float s = fmaf(scale, drx + gz1, base);
            s = fminf(fmaxf(s, 0.0f), (float)(NS - 1));
            const float i0f = fminf(floorf(s), (float)(NS - 2));
            const int   i0  = (int)i0f;
            const float w  = s - i0f;
            const float wm = 1.0f - w;
            const uint2 t0v = row[i0];
            const uint2 t1v = row[i0 + 1];
            const float2 f0 = __half22float2(*(const __half2*)&t0v.x);
            const float2 f1 = __half22float2(*(const __half2*)&t0v.y);
            const float2 f2 = __half22float2(*(const __half2*)&t1v.x);
            const float2 f3 = __half22float2(*(const __half2*)&t1v.y);
            a1.x = fmaf(wm, f0.x, fmaf(w, f2.x, a1.x));
            a1.y = fmaf(wm, f0.y, fmaf(w, f2.y, a1.y));
            a1.z = fmaf(wm, f1.x, fmaf(w, f3.x, a1.z));
            a1.w = fmaf(wm, f1.y, fmaf(w, f3.y, a1.w));
        }

        __syncthreads();   // orders this iter's reads & next-buffer writes
    }

    float4* part = d_part + ((size_t)half * BB + bb) * MM;
    part[m0] = a0;
    part[m1] = a1;
}

__global__ void combine_kernel(float* __restrict__ out) {
    const int t = blockIdx.x * blockDim.x + threadIdx.x;   // 0 .. BB*MM-1
    if (t >= BB * MM) return;
    const float4 u = d_part[t];
    const float4 v = d_part[BB * MM + t];
    ((float4*)out)[t] = make_float4(u.x + v.x, u.y + v.y, u.z + v.z, u.w + v.w);
}

extern "C" void kernel_launch(void* const* d_in, const int* in_sizes, int n_in,
                              void* d_out, int out_size) {
    const float* rf = (const float*)d_in[0];
    const float* g  = (const float*)d_in[1];
    const float* pr = (const float*)d_in[2];
    const float* p  = (const float*)d_in[3];
    float* out = (float*)d_out;

    pack_kernel<<<(BB * NC * NS4 + 255) / 256, 256>>>(rf);

    das_kernel<<<BB * PTILES * 2, DTHREADS>>>(g, pr, p);

    combine_kernel<<<(BB * MM + 255) / 256, 256>>>(out);
}

// round 13
// speedup vs baseline: 1.2465x; 1.0647x over previous
#include <cuda_runtime.h>
#include <cuda_fp16.h>
#include <cuda_bf16.h>

#define BB 2
#define NC 128
#define NS 2048
#define NZ 256
#define NX 256
#define KK 4
#define MM (NZ * NX)

#define DTHREADS 1024
#define PXB 2048                         // pixels per block (2 per thread)
#define CHALF (NC / 2)                   // channels per block (split 2-way)
#define PTILES (MM / PXB)                // 32 pixel tiles per batch
#define CHG 2                            // channels staged per group
#define NGRP (CHALF / CHG)               // 32 groups per block
#define GRP_SLOTS (CHG * NS)             // uint4 slots per group buffer: 4096
#define SMEM_BYTES (2 * GRP_SLOTS * 16 + NC * 16 + 16)

// fp16 PAIR-packed rf: d_rfp[(b*NC+c)*NS + s] = 8 halves {rf[s,0:4], rf[s+1,0:4]} (16B)
__device__ uint4  d_rfp[BB * NC * NS];
// Partial sums: [half][b][pixel] as float4
__device__ float4 d_part[2 * BB * MM];

__global__ void pack_kernel(const float* __restrict__ rf) {
    const int t = blockIdx.x * blockDim.x + threadIdx.x;   // 0 .. BB*NC*NS-1
    if (t >= BB * NC * NS) return;
    const int s = t & (NS - 1);
    const float4* rf4 = (const float4*)rf;
    const float4 y0 = rf4[t];
    const float4 y1 = rf4[t + (s < NS - 1 ? 1 : 0)];
    __half2 h0 = __floats2half2_rn(y0.x, y0.y);
    __half2 h1 = __floats2half2_rn(y0.z, y0.w);
    __half2 h2 = __floats2half2_rn(y1.x, y1.y);
    __half2 h3 = __floats2half2_rn(y1.z, y1.w);
    uint4 v;
    v.x = *(unsigned*)&h0;
    v.y = *(unsigned*)&h1;
    v.z = *(unsigned*)&h2;
    v.w = *(unsigned*)&h3;
    d_rfp[t] = v;
}

extern __shared__ uint4 dyn_smem[];   // [2][GRP_SLOTS] buffers, then pr, then params

__global__ __launch_bounds__(DTHREADS, 1) void das_kernel(
    const float* __restrict__ g,    // [B, NZ, NX, 3]
    const float* __restrict__ pr,   // [B, NC, 3]
    const float* __restrict__ p)    // [B, 4]
{
    uint4*  buf  = dyn_smem;                                  // 2 x 64KB
    float4* s_pr = (float4*)(dyn_smem + 2 * GRP_SLOTS);
    float*  s_pm = (float*)(s_pr + NC);

    const int tid  = threadIdx.x;
    const int half = blockIdx.x & 1;
    const int tile = (blockIdx.x >> 1) & (PTILES - 1);
    const int bb   = blockIdx.x / (2 * PTILES);

    const int m0 = tile * PXB + tid;
    const int m1 = m0 + DTHREADS;
    const int c0 = half * CHALF;

    if (tid < NC) {
        const float* q = pr + ((size_t)bb * NC + tid) * 3;
        s_pr[tid] = make_float4(q[0], q[1], q[2], 0.0f);
    }
    if (tid == 0) {
        const float cc = p[bb * 4 + 0];
        const float fs = p[bb * 4 + 1];
        const float t0 = p[bb * 4 + 2];
        s_pm[0] = fs / cc;
        s_pm[1] = fs * t0 / cc;
    }

    const float* gp0 = g + ((size_t)bb * MM + m0) * 3;
    const float* gp1 = g + ((size_t)bb * MM + m1) * 3;
    const float gx0 = gp0[0], gy0 = gp0[1], gz0 = gp0[2];
    const float gx1 = gp1[0], gy1 = gp1[1], gz1 = gp1[2];

    const uint4* __restrict__ rfg = d_rfp + ((size_t)bb * NC + c0) * NS;

    // Stage group 0; prefetch group 1 into regs.
    #pragma unroll
    for (int i = 0; i < 4; ++i) buf[i * DTHREADS + tid] = rfg[i * DTHREADS + tid];
    uint4 nxt[4];
    #pragma unroll
    for (int i = 0; i < 4; ++i) nxt[i] = rfg[GRP_SLOTS + i * DTHREADS + tid];
    __syncthreads();   // params + buf0 visible

    const float scale = s_pm[0];
    const float base  = s_pm[1];

    float4 a0 = make_float4(0.f, 0.f, 0.f, 0.f);
    float4 a1 = make_float4(0.f, 0.f, 0.f, 0.f);

    for (int grp = 0; grp < NGRP; ++grp) {
        // Write buffer for group grp+1 (prefetched during grp-1).
        // Safe: last reads of buf[(grp+1)&1] were in iter grp-1, ordered by its sync.
        if (grp + 1 < NGRP) {
            uint4* dst = buf + ((grp + 1) & 1) * GRP_SLOTS;
            #pragma unroll
            for (int i = 0; i < 4; ++i) dst[i * DTHREADS + tid] = nxt[i];
        }
        // Prefetch group grp+2.
        if (grp + 2 < NGRP) {
            const uint4* src = rfg + (size_t)(grp + 2) * GRP_SLOTS;
            #pragma unroll
            for (int i = 0; i < 4; ++i) nxt[i] = src[i * DTHREADS + tid];
        }

        const uint4* gbuf = buf + (grp & 1) * GRP_SLOTS;

        #pragma unroll
        for (int ch = 0; ch < CHG; ++ch) {
            const float4 pc = s_pr[c0 + grp * CHG + ch];
            const uint4* row = gbuf + ch * NS;

            // pixel 0
            {
                const float dx = gx0 - pc.x, dy = gy0 - pc.y, dz = gz0 - pc.z;
                const float r2 = fmaf(dx, dx, fmaf(dy, dy, dz * dz));
                float drx; asm("sqrt.approx.f32 %0, %1;" : "=f"(drx) : "f"(r2));
                float s = fmaf(scale, drx + gz0, base);
                s = fminf(fmaxf(s, 0.0f), (float)(NS - 1));
                const float i0f = fminf(floorf(s), (float)(NS - 2));
                const int   i0  = (int)i0f;
                const float w  = s - i0f;
                const float wm = 1.0f - w;
                const uint4 v = row[i0];                 // ONE LDS.128: both taps
                const float2 f0 = __half22float2(*(const __half2*)&v.x);
                const float2 f1 = __half22float2(*(const __half2*)&v.y);
                const float2 f2 = __half22float2(*(const __half2*)&v.z);
                const float2 f3 = __half22float2(*(const __half2*)&v.w);
                a0.x = fmaf(wm, f0.x, fmaf(w, f2.x, a0.x));
                a0.y = fmaf(wm, f0.y, fmaf(w, f2.y, a0.y));
                a0.z = fmaf(wm, f1.x, fmaf(w, f3.x, a0.z));
                a0.w = fmaf(wm, f1.y, fmaf(w, f3.y, a0.w));
            }
            // pixel 1
            {
                const float dx = gx1 - pc.x, dy = gy1 - pc.y, dz = gz1 - pc.z;
                const float r2 = fmaf(dx, dx, fmaf(dy, dy, dz * dz));
                float drx; asm("sqrt.approx.f32 %0, %1;" : "=f"(drx) : "f"(r2));
                float s = fmaf(scale, drx + gz1, base);
                s = fminf(fmaxf(s, 0.0f), (float)(NS - 1));
                const float i0f = fminf(floorf(s), (float)(NS - 2));
                const int   i0  = (int)i0f;
                const float w  = s - i0f;
                const float wm = 1.0f - w;
                const uint4 v = row[i0];
                const float2 f0 = __half22float2(*(const __half2*)&v.x);
                const float2 f1 = __half22float2(*(const __half2*)&v.y);
                const float2 f2 = __half22float2(*(const __half2*)&v.z);
                const float2 f3 = __half22float2(*(const __half2*)&v.w);
                a1.x = fmaf(wm, f0.x, fmaf(w, f2.x, a1.x));
                a1.y = fmaf(wm, f0.y, fmaf(w, f2.y, a1.y));
                a1.z = fmaf(wm, f1.x, fmaf(w, f3.x, a1.z));
                a1.w = fmaf(wm, f1.y, fmaf(w, f3.y, a1.w));
            }
        }

        __syncthreads();   // one barrier per 2 channels
    }

    float4* part = d_part + ((size_t)half * BB + bb) * MM;
    part[m0] = a0;
    part[m1] = a1;
}

__global__ void combine_kernel(float* __restrict__ out) {
    const int t = blockIdx.x * blockDim.x + threadIdx.x;   // 0 .. BB*MM-1
    if (t >= BB * MM) return;
    const float4 u = d_part[t];
    const float4 v = d_part[BB * MM + t];
    ((float4*)out)[t] = make_float4(u.x + v.x, u.y + v.y, u.z + v.z, u.w + v.w);
}

extern "C" void kernel_launch(void* const* d_in, const int* in_sizes, int n_in,
                              void* d_out, int out_size) {
    const float* rf = (const float*)d_in[0];
    const float* g  = (const float*)d_in[1];
    const float* pr = (const float*)d_in[2];
    const float* p  = (const float*)d_in[3];
    float* out = (float*)d_out;

    // Unconditional (idempotent host-side call; not a stream op, no static guard).
    cudaFuncSetAttribute(das_kernel,
                         cudaFuncAttributeMaxDynamicSharedMemorySize, SMEM_BYTES);

    pack_kernel<<<(BB * NC * NS + 255) / 256, 256>>>(rf);

    das_kernel<<<BB * PTILES * 2, DTHREADS, SMEM_BYTES>>>(g, pr, p);

    combine_kernel<<<(BB * MM + 255) / 256, 256>>>(out);
}